// round 1
// baseline (speedup 1.0000x reference)
#include <cuda_runtime.h>
#include <cstdint>
#include <math.h>

#define B 512
#define IN_DIM 1024
#define H 512
#define E_DIM 512
#define V 2048
#define MAX_LEN 32
#define L 33

// ---------------- scratch (no allocations allowed) ----------------
__device__ float g_h[B * H];
__device__ float g_c[B * H];
__device__ float g_e[B * E_DIM];
__device__ float g_gates[(size_t)B * 4 * H];
__device__ float g_logits[(size_t)B * V];

// ---------------- threefry2x32 (JAX-compatible, 20 rounds) ----------------
__host__ __device__ __forceinline__ uint32_t rotl32(uint32_t v, int d) {
    return (v << d) | (v >> (32 - d));
}

__host__ __device__ __forceinline__ void threefry2x32(uint32_t k0, uint32_t k1,
                                                      uint32_t x0, uint32_t x1,
                                                      uint32_t& o0, uint32_t& o1) {
    uint32_t ks2 = k0 ^ k1 ^ 0x1BD11BDAu;
    x0 += k0; x1 += k1;
#define TF_R(r) { x0 += x1; x1 = rotl32(x1, r); x1 ^= x0; }
    TF_R(13) TF_R(15) TF_R(26) TF_R(6)
    x0 += k1; x1 += ks2 + 1u;
    TF_R(17) TF_R(29) TF_R(16) TF_R(24)
    x0 += ks2; x1 += k0 + 2u;
    TF_R(13) TF_R(15) TF_R(26) TF_R(6)
    x0 += k0; x1 += k1 + 3u;
    TF_R(17) TF_R(29) TF_R(16) TF_R(24)
    x0 += k1; x1 += ks2 + 4u;
    TF_R(13) TF_R(15) TF_R(26) TF_R(6)
    x0 += ks2; x1 += k0 + 5u;
#undef TF_R
    o0 = x0; o1 = x1;
}

__device__ __forceinline__ float sigmoidf_(float x) {
    // XLA logistic expansion: 0.5 + 0.5 * tanh(0.5 * x)
    return 0.5f + 0.5f * tanhf(0.5f * x);
}

// ---------------- generic fp32 GEMM: C = A@W1 (+ A2@W2) + b1 (+ b2) ----------------
// Tiles: 64x64, BK=16, 256 threads, 4x4 per thread. All dims are multiples.
#define BM 64
#define BN 64
#define BK 16

__global__ __launch_bounds__(256) void gemm_kernel(
    const float* __restrict__ A,  const float* __restrict__ W,  const float* __restrict__ bias,
    float* __restrict__ C, int M, int N, int K,
    const float* __restrict__ A2, const float* __restrict__ W2, const float* __restrict__ bias2, int K2)
{
    __shared__ float As[BK][BM];
    __shared__ float Ws[BK][BN];

    int tid = threadIdx.x;
    int tx = tid & 15;       // 0..15 (cols)
    int ty = tid >> 4;       // 0..15 (rows)
    int row0 = blockIdx.y * BM;
    int col0 = blockIdx.x * BN;

    float acc[4][4];
#pragma unroll
    for (int i = 0; i < 4; i++)
#pragma unroll
        for (int j = 0; j < 4; j++) acc[i][j] = 0.f;

    for (int pass = 0; pass < 2; ++pass) {
        const float* Ap = (pass == 0) ? A : A2;
        const float* Wp = (pass == 0) ? W : W2;
        int Kp = (pass == 0) ? K : K2;
        if (Ap == nullptr) break;

        for (int k0 = 0; k0 < Kp; k0 += BK) {
            // A tile: 64 rows x 16 k, float4 per thread
            {
                int r  = tid >> 2;          // 0..63
                int kk = (tid & 3) * 4;     // 0,4,8,12
                float4 v = *reinterpret_cast<const float4*>(Ap + (size_t)(row0 + r) * Kp + k0 + kk);
                As[kk + 0][r] = v.x; As[kk + 1][r] = v.y;
                As[kk + 2][r] = v.z; As[kk + 3][r] = v.w;
            }
            // W tile: 16 k x 64 n, float4 per thread
            {
                int kk = tid >> 4;          // 0..15
                int nn = (tid & 15) * 4;    // 0..60
                float4 v = *reinterpret_cast<const float4*>(Wp + (size_t)(k0 + kk) * N + col0 + nn);
                *reinterpret_cast<float4*>(&Ws[kk][nn]) = v;
            }
            __syncthreads();
#pragma unroll
            for (int k = 0; k < BK; ++k) {
                float4 a4 = *reinterpret_cast<const float4*>(&As[k][ty * 4]);
                float4 w4 = *reinterpret_cast<const float4*>(&Ws[k][tx * 4]);
                float a[4] = {a4.x, a4.y, a4.z, a4.w};
                float w[4] = {w4.x, w4.y, w4.z, w4.w};
#pragma unroll
                for (int i = 0; i < 4; i++)
#pragma unroll
                    for (int j = 0; j < 4; j++)
                        acc[i][j] = fmaf(a[i], w[j], acc[i][j]);
            }
            __syncthreads();
        }
    }

#pragma unroll
    for (int i = 0; i < 4; i++) {
        int r = row0 + ty * 4 + i;
#pragma unroll
        for (int j = 0; j < 4; j++) {
            int cc = col0 + tx * 4 + j;
            float v = acc[i][j];
            if (bias)  v += bias[cc];
            if (bias2) v += bias2[cc];
            C[(size_t)r * N + cc] = v;
        }
    }
}

// ---------------- init: c = 0, e = broadcast(sos) ----------------
__global__ void init_kernel(const float* __restrict__ sos) {
    int idx = blockIdx.x * blockDim.x + threadIdx.x;
    if (idx < B * E_DIM) {
        g_c[idx] = 0.f;
        g_e[idx] = sos[idx & (E_DIM - 1)];
    }
}

// ---------------- LSTM pointwise: gates -> h, c ----------------
__global__ void lstm_kernel() {
    int idx = blockIdx.x * blockDim.x + threadIdx.x;
    if (idx >= B * H) return;
    int b = idx >> 9;          // /512
    int j = idx & (H - 1);
    const float* gr = g_gates + (size_t)b * 4 * H;
    float ig = sigmoidf_(gr[j]);
    float fg = sigmoidf_(gr[H + j]);
    float gg = tanhf(gr[2 * H + j]);
    float og = sigmoidf_(gr[3 * H + j]);
    float cn = fg * g_c[idx] + ig * gg;
    float hn = og * tanhf(cn);
    g_c[idx] = cn;
    g_h[idx] = hn;
}

// ---------------- softmax + gumbel sample + outputs + embedding gather ----------------
__global__ __launch_bounds__(256) void sample_kernel(
    const float* __restrict__ embedding,
    float* __restrict__ o_seq, float* __restrict__ o_probs,
    float* __restrict__ o_logp, float* __restrict__ o_ent,
    uint32_t sk0, uint32_t sk1, int t)
{
    __shared__ float sred[256];
    __shared__ int   sredi[256];
    __shared__ float s_rowmax, s_lse;
    __shared__ int   s_sym;

    int b = blockIdx.x;
    int tid = threadIdx.x;
    const float* lr = g_logits + (size_t)b * V;

    // row max
    float m = -3.402823466e38f;
    for (int v = tid; v < V; v += 256) m = fmaxf(m, lr[v]);
    sred[tid] = m; __syncthreads();
    for (int s = 128; s > 0; s >>= 1) {
        if (tid < s) sred[tid] = fmaxf(sred[tid], sred[tid + s]);
        __syncthreads();
    }
    if (tid == 0) s_rowmax = sred[0];
    __syncthreads();
    float rowmax = s_rowmax;

    // log-sum-exp
    float sum = 0.f;
    for (int v = tid; v < V; v += 256) sum += expf(lr[v] - rowmax);
    sred[tid] = sum; __syncthreads();
    for (int s = 128; s > 0; s >>= 1) {
        if (tid < s) sred[tid] += sred[tid + s];
        __syncthreads();
    }
    if (tid == 0) s_lse = logf(sred[0]);
    __syncthreads();
    float lse = s_lse;

    // probs / entropy / gumbel argmax
    float entacc = 0.f;
    float best = -3.402823466e38f;
    int bestv = V;
    size_t pbase = ((size_t)b * L + t) * V;
    const float TINY = 1.17549435e-38f;
    for (int v = tid; v < V; v += 256) {
        float lsm = lr[v] - rowmax - lse;
        float p = expf(lsm);
        o_probs[pbase + v] = p;
        entacc += p * lsm;
        // JAX partitionable random_bits: bits = o0 ^ o1 of threefry(sk, (0, flat))
        uint32_t o0, o1;
        threefry2x32(sk0, sk1, 0u, (uint32_t)(b * V + v), o0, o1);
        uint32_t bits = o0 ^ o1;
        float uf = __uint_as_float(0x3f800000u | (bits >> 9)) - 1.0f;
        float u = fmaxf(TINY, uf + TINY);
        float g = -logf(-logf(u));
        float sc = lsm + g;
        if (sc > best) { best = sc; bestv = v; }
    }

    // entropy reduce
    __syncthreads();
    sred[tid] = entacc; __syncthreads();
    for (int s = 128; s > 0; s >>= 1) {
        if (tid < s) sred[tid] += sred[tid + s];
        __syncthreads();
    }
    float entropy = -sred[0];
    __syncthreads();

    // argmax reduce (first-index tie-break)
    sred[tid] = best; sredi[tid] = bestv; __syncthreads();
    for (int s = 128; s > 0; s >>= 1) {
        if (tid < s) {
            float ov = sred[tid + s]; int oi = sredi[tid + s];
            if (ov > sred[tid] || (ov == sred[tid] && oi < sredi[tid])) {
                sred[tid] = ov; sredi[tid] = oi;
            }
        }
        __syncthreads();
    }
    if (tid == 0) {
        int sym = sredi[0];
        s_sym = sym;
        o_seq[b * L + t] = (float)sym;
        o_ent[b * L + t] = entropy;
        o_logp[b * L + t] = lr[sym] - rowmax - lse;
    }
    __syncthreads();
    int sym = s_sym;
    for (int j = tid; j < E_DIM; j += 256)
        g_e[b * E_DIM + j] = embedding[(size_t)sym * E_DIM + j];
}

// ---------------- EOS step (t = 32): zeros + probs of ones ----------------
__global__ void eos_kernel(float* __restrict__ o_seq, float* __restrict__ o_probs,
                           float* __restrict__ o_logp, float* __restrict__ o_ent) {
    int idx = blockIdx.x * blockDim.x + threadIdx.x;
    if (idx < B * V) {
        int b = idx / V, v = idx % V;
        o_probs[((size_t)b * L + MAX_LEN) * V + v] = 1.0f;
    }
    if (idx < B) {
        o_seq[idx * L + MAX_LEN]  = 0.f;
        o_logp[idx * L + MAX_LEN] = 0.f;
        o_ent[idx * L + MAX_LEN]  = 0.f;
    }
}

// ---------------- launch ----------------
extern "C" void kernel_launch(void* const* d_in, const int* in_sizes, int n_in,
                              void* d_out, int out_size) {
    const float* x         = (const float*)d_in[0];
    const float* agent_w   = (const float*)d_in[1];
    const float* agent_b   = (const float*)d_in[2];
    const float* sos       = (const float*)d_in[3];
    const float* embedding = (const float*)d_in[4];
    const float* w_ih      = (const float*)d_in[5];
    const float* w_hh      = (const float*)d_in[6];
    const float* b_ih      = (const float*)d_in[7];
    const float* b_hh      = (const float*)d_in[8];
    const float* out_w     = (const float*)d_in[9];
    const float* out_b     = (const float*)d_in[10];

    float* out = (float*)d_out;
    float* o_seq   = out;                                   // [B, 33]
    float* o_probs = out + (size_t)B * L;                   // [B, 33, V]
    float* o_logp  = o_probs + (size_t)B * L * V;           // [B, 33]
    float* o_ent   = o_logp + (size_t)B * L;                // [B, 33]

    static float *dh = nullptr, *dc = nullptr, *de = nullptr, *dg = nullptr, *dl = nullptr;
    if (!dh) {
        cudaGetSymbolAddress((void**)&dh, g_h);
        cudaGetSymbolAddress((void**)&dc, g_c);
        cudaGetSymbolAddress((void**)&de, g_e);
        cudaGetSymbolAddress((void**)&dg, g_gates);
        cudaGetSymbolAddress((void**)&dl, g_logits);
    }

    init_kernel<<<(B * E_DIM + 255) / 256, 256>>>(sos);

    // h0 = x @ agent_w + agent_b
    gemm_kernel<<<dim3(H / BN, B / BM), 256>>>(
        x, agent_w, agent_b, dh, B, H, IN_DIM, nullptr, nullptr, nullptr, 0);

    // JAX key chain: key0 = key(1) = (0,1); split (partitionable/foldlike):
    //   key' = threefry(key,(0,0)), sk = threefry(key,(0,1))
    uint32_t k0 = 0u, k1 = 1u;
    for (int t = 0; t < MAX_LEN; ++t) {
        uint32_t n0, n1, s0, s1;
        threefry2x32(k0, k1, 0u, 0u, n0, n1);
        threefry2x32(k0, k1, 0u, 1u, s0, s1);

        // gates = e @ w_ih + h @ w_hh + b_ih + b_hh
        gemm_kernel<<<dim3(4 * H / BN, B / BM), 256>>>(
            de, w_ih, b_ih, dg, B, 4 * H, E_DIM, dh, w_hh, b_hh, H);

        lstm_kernel<<<(B * H + 255) / 256, 256>>>();

        // logits = h @ out_w + out_b
        gemm_kernel<<<dim3(V / BN, B / BM), 256>>>(
            dh, out_w, out_b, dl, B, V, H, nullptr, nullptr, nullptr, 0);

        sample_kernel<<<B, 256>>>(embedding, o_seq, o_probs, o_logp, o_ent, s0, s1, t);

        k0 = n0; k1 = n1;
    }

    eos_kernel<<<(B * V + 255) / 256, 256>>>(o_seq, o_probs, o_logp, o_ent);
}

// round 2
// speedup vs baseline: 2.0411x; 2.0411x over previous
#include <cuda_runtime.h>
#include <cstdint>
#include <math.h>

#define B 512
#define IN_DIM 1024
#define H 512
#define E_DIM 512
#define V 2048
#define MAX_LEN 32
#define L 33
#define G4H (4 * H)

// ---------------- scratch (no allocations allowed) ----------------
__device__ float g_h[B * H];
__device__ float g_c[B * H];
__device__ float g_Pg[(size_t)B * G4H];        // h @ w_hh partial gates
__device__ float g_logits[(size_t)B * V];
__device__ float g_eproj[(size_t)V * G4H];     // embedding @ w_ih + b_ih + b_hh
__device__ float g_sosproj[G4H];               // sos @ w_ih + b_ih + b_hh
__device__ int   g_sym[B];

// ---------------- threefry2x32 (JAX-compatible, 20 rounds) ----------------
__host__ __device__ __forceinline__ uint32_t rotl32(uint32_t v, int d) {
    return (v << d) | (v >> (32 - d));
}

__host__ __device__ __forceinline__ void threefry2x32(uint32_t k0, uint32_t k1,
                                                      uint32_t x0, uint32_t x1,
                                                      uint32_t& o0, uint32_t& o1) {
    uint32_t ks2 = k0 ^ k1 ^ 0x1BD11BDAu;
    x0 += k0; x1 += k1;
#define TF_R(r) { x0 += x1; x1 = rotl32(x1, r); x1 ^= x0; }
    TF_R(13) TF_R(15) TF_R(26) TF_R(6)
    x0 += k1; x1 += ks2 + 1u;
    TF_R(17) TF_R(29) TF_R(16) TF_R(24)
    x0 += ks2; x1 += k0 + 2u;
    TF_R(13) TF_R(15) TF_R(26) TF_R(6)
    x0 += k0; x1 += k1 + 3u;
    TF_R(17) TF_R(29) TF_R(16) TF_R(24)
    x0 += k1; x1 += ks2 + 4u;
    TF_R(13) TF_R(15) TF_R(26) TF_R(6)
    x0 += ks2; x1 += k0 + 5u;
#undef TF_R
    o0 = x0; o1 = x1;
}

__device__ __forceinline__ float sigmoidf_(float x) {
    // XLA logistic expansion: 0.5 + 0.5 * tanh(0.5 * x)
    return 0.5f + 0.5f * tanhf(0.5f * x);
}

// ---------------- packed f32x2 helpers ----------------
__device__ __forceinline__ void ffma2(unsigned long long& acc, unsigned long long a,
                                      unsigned long long b) {
    asm("fma.rn.f32x2 %0, %1, %2, %0;" : "+l"(acc) : "l"(a), "l"(b));
}
__device__ __forceinline__ unsigned long long dup2(float w) {
    unsigned long long r;
    asm("mov.b64 %0, {%1, %1};" : "=l"(r) : "r"(__float_as_uint(w)));
    return r;
}
__device__ __forceinline__ float2 unpack2(unsigned long long v) {
    float2 f;
    asm("mov.b64 {%0, %1}, %2;" : "=f"(f.x), "=f"(f.y) : "l"(v));
    return f;
}

// ---------------- FFMA2 GEMM: C = A @ W (+bias), split-column dual output ----------
// Tiles: BM=128, BN=128, BK=16, 256 threads, 8x8 per thread (4 f32x2 row-pairs x 8 cols).
// Columns [0, N1) -> W1/C1 (+b1a +b1b); columns [N1, N1+N2) -> W2/C2 (+b2a).
#define BM 128
#define BN 128
#define BK 16
#define ASTRIDE 130   // pad: conflict-free transpose stores, 8B-aligned rows
#define WSTRIDE 132   // pad: conflict-free dual-row stores, 16B-aligned rows

__global__ __launch_bounds__(256, 2) void gemm2_kernel(
    const float* __restrict__ A, int K,
    const float* __restrict__ W1, const float* __restrict__ b1a, const float* __restrict__ b1b,
    float* __restrict__ C1, int N1,
    const float* __restrict__ W2, const float* __restrict__ b2a,
    float* __restrict__ C2, int N2, int col_base)
{
    __shared__ float As[2][BK][ASTRIDE];
    __shared__ float Ws[2][BK][WSTRIDE];

    const int tid = threadIdx.x;
    const int tx = tid & 15;           // 0..15 (N)
    const int ty = tid >> 4;           // 0..15 (M)
    const int row0 = blockIdx.y * BM;
    const int col0 = blockIdx.x * BN + col_base;

    const float* W; const float* ba; const float* bb; float* C; int ldN; int cloc0;
    if (col0 < N1) { W = W1; ba = b1a; bb = b1b; C = C1; ldN = N1; cloc0 = col0; }
    else           { W = W2; ba = b2a; bb = nullptr; C = C2; ldN = N2; cloc0 = col0 - N1; }

    // loader indices
    const int lrA  = tid >> 2;               // 0..63
    const int lkk4 = (tid & 3) * 4;          // 0,4,8,12
    const int lkkw = tid >> 4;               // 0..15
    const int lnn4 = (tid & 15) * 4;         // 0..60

    const float* Arow0 = A + (size_t)(row0 + lrA) * K + lkk4;
    const float* Arow1 = A + (size_t)(row0 + lrA + 64) * K + lkk4;
    const float* Wrow  = W + (size_t)lkkw * ldN + cloc0;

    unsigned long long acc[4][8];
#pragma unroll
    for (int p = 0; p < 4; p++)
#pragma unroll
        for (int j = 0; j < 8; j++) acc[p][j] = 0ull;

    const int KT = K / BK;
    float4 fa0, fa1, fw0, fw1;

    // prefetch tile 0
    fa0 = *reinterpret_cast<const float4*>(Arow0);
    fa1 = *reinterpret_cast<const float4*>(Arow1);
    fw0 = *reinterpret_cast<const float4*>(Wrow + lnn4);
    fw1 = *reinterpret_cast<const float4*>(Wrow + 64 + lnn4);
    {
        float av0[4] = {fa0.x, fa0.y, fa0.z, fa0.w};
        float av1[4] = {fa1.x, fa1.y, fa1.z, fa1.w};
#pragma unroll
        for (int i = 0; i < 4; i++) {
            As[0][lkk4 + i][lrA] = av0[i];
            As[0][lkk4 + i][lrA + 64] = av1[i];
        }
        *reinterpret_cast<float4*>(&Ws[0][lkkw][lnn4]) = fw0;
        *reinterpret_cast<float4*>(&Ws[0][lkkw][64 + lnn4]) = fw1;
    }

    int buf = 0;
    for (int t = 0; t < KT; ++t) {
        __syncthreads();
        if (t + 1 < KT) {
            int k0 = (t + 1) * BK;
            fa0 = *reinterpret_cast<const float4*>(Arow0 + k0);
            fa1 = *reinterpret_cast<const float4*>(Arow1 + k0);
            fw0 = *reinterpret_cast<const float4*>(Wrow + (size_t)k0 * ldN + lnn4);
            fw1 = *reinterpret_cast<const float4*>(Wrow + (size_t)k0 * ldN + 64 + lnn4);
        }

#pragma unroll
        for (int kk = 0; kk < BK; ++kk) {
            const unsigned long long* ap0 =
                reinterpret_cast<const unsigned long long*>(&As[buf][kk][ty * 4]);
            const unsigned long long* ap1 =
                reinterpret_cast<const unsigned long long*>(&As[buf][kk][64 + ty * 4]);
            unsigned long long a01 = ap0[0];
            unsigned long long a23 = ap0[1];
            unsigned long long a45 = ap1[0];
            unsigned long long a67 = ap1[1];
            float4 w03 = *reinterpret_cast<const float4*>(&Ws[buf][kk][tx * 4]);
            float4 w47 = *reinterpret_cast<const float4*>(&Ws[buf][kk][64 + tx * 4]);
            unsigned long long wd[8];
            wd[0] = dup2(w03.x); wd[1] = dup2(w03.y); wd[2] = dup2(w03.z); wd[3] = dup2(w03.w);
            wd[4] = dup2(w47.x); wd[5] = dup2(w47.y); wd[6] = dup2(w47.z); wd[7] = dup2(w47.w);
#pragma unroll
            for (int j = 0; j < 8; j++) {
                ffma2(acc[0][j], a01, wd[j]);
                ffma2(acc[1][j], a23, wd[j]);
                ffma2(acc[2][j], a45, wd[j]);
                ffma2(acc[3][j], a67, wd[j]);
            }
        }

        if (t + 1 < KT) {
            int nb = buf ^ 1;
            float av0[4] = {fa0.x, fa0.y, fa0.z, fa0.w};
            float av1[4] = {fa1.x, fa1.y, fa1.z, fa1.w};
#pragma unroll
            for (int i = 0; i < 4; i++) {
                As[nb][lkk4 + i][lrA] = av0[i];
                As[nb][lkk4 + i][lrA + 64] = av1[i];
            }
            *reinterpret_cast<float4*>(&Ws[nb][lkkw][lnn4]) = fw0;
            *reinterpret_cast<float4*>(&Ws[nb][lkkw][64 + lnn4]) = fw1;
        }
        buf ^= 1;
    }

    // epilogue: bias + store (float4 per row / col-group)
    float bv[2][4];
#pragma unroll
    for (int g = 0; g < 2; g++) {
        int cb = cloc0 + g * 64 + tx * 4;
#pragma unroll
        for (int jj = 0; jj < 4; jj++) {
            float v = 0.f;
            if (ba) v += ba[cb + jj];
            if (bb) v += bb[cb + jj];
            bv[g][jj] = v;
        }
    }
#pragma unroll
    for (int hh = 0; hh < 2; hh++) {
#pragma unroll
        for (int pp = 0; pp < 2; pp++) {
            int p = hh * 2 + pp;
            float2 f[8];
#pragma unroll
            for (int j = 0; j < 8; j++) f[j] = unpack2(acc[p][j]);
            int rbase = row0 + hh * 64 + ty * 4 + 2 * pp;
#pragma unroll
            for (int lane = 0; lane < 2; lane++) {
                int r = rbase + lane;
#pragma unroll
                for (int g = 0; g < 2; g++) {
                    int c = cloc0 + g * 64 + tx * 4;
                    float4 o;
                    o.x = (lane ? f[g * 4 + 0].y : f[g * 4 + 0].x) + bv[g][0];
                    o.y = (lane ? f[g * 4 + 1].y : f[g * 4 + 1].x) + bv[g][1];
                    o.z = (lane ? f[g * 4 + 2].y : f[g * 4 + 2].x) + bv[g][2];
                    o.w = (lane ? f[g * 4 + 3].y : f[g * 4 + 3].x) + bv[g][3];
                    *reinterpret_cast<float4*>(&C[(size_t)r * ldN + c]) = o;
                }
            }
        }
    }
}

// ---------------- sos projection: sos @ w_ih + b_ih + b_hh ----------------
__global__ void sosproj_kernel(const float* __restrict__ sos, const float* __restrict__ w_ih,
                               const float* __restrict__ b_ih, const float* __restrict__ b_hh) {
    int n = blockIdx.x * blockDim.x + threadIdx.x;
    float acc = 0.f;
    for (int k = 0; k < E_DIM; ++k)
        acc = fmaf(__ldg(&sos[k]), w_ih[(size_t)k * G4H + n], acc);
    g_sosproj[n] = acc + b_ih[n] + b_hh[n];
}

// ---------------- init: c = 0 ----------------
__global__ void init_kernel() {
    int idx = blockIdx.x * blockDim.x + threadIdx.x;
    if (idx < B * H) g_c[idx] = 0.f;
}

// ---------------- LSTM pointwise: Pg + proj-row(sym) -> h, c ----------------
__global__ void lstm_kernel(int t) {
    int idx = blockIdx.x * blockDim.x + threadIdx.x;
    if (idx >= B * H) return;
    int b = idx >> 9;
    int j = idx & (H - 1);
    const float* pr = g_Pg + (size_t)b * G4H;
    const float* ep = (t == 0) ? g_sosproj : (g_eproj + (size_t)g_sym[b] * G4H);
    float ig = sigmoidf_(pr[j] + ep[j]);
    float fg = sigmoidf_(pr[H + j] + ep[H + j]);
    float gg = tanhf(pr[2 * H + j] + ep[2 * H + j]);
    float og = sigmoidf_(pr[3 * H + j] + ep[3 * H + j]);
    float cn = fg * g_c[idx] + ig * gg;
    float hn = og * tanhf(cn);
    g_c[idx] = cn;
    g_h[idx] = hn;
}

// ---------------- softmax + gumbel sample + outputs ----------------
__global__ __launch_bounds__(256) void sample_kernel(
    float* __restrict__ o_seq, float* __restrict__ o_probs,
    float* __restrict__ o_logp, float* __restrict__ o_ent,
    uint32_t sk0, uint32_t sk1, int t)
{
    __shared__ float sred[256];
    __shared__ int   sredi[256];
    __shared__ float s_rowmax, s_lse;

    int b = blockIdx.x;
    int tid = threadIdx.x;
    const float* lr = g_logits + (size_t)b * V;

    // row max
    float m = -3.402823466e38f;
    for (int v = tid; v < V; v += 256) m = fmaxf(m, lr[v]);
    sred[tid] = m; __syncthreads();
    for (int s = 128; s > 0; s >>= 1) {
        if (tid < s) sred[tid] = fmaxf(sred[tid], sred[tid + s]);
        __syncthreads();
    }
    if (tid == 0) s_rowmax = sred[0];
    __syncthreads();
    float rowmax = s_rowmax;

    // log-sum-exp
    float sum = 0.f;
    for (int v = tid; v < V; v += 256) sum += expf(lr[v] - rowmax);
    sred[tid] = sum; __syncthreads();
    for (int s = 128; s > 0; s >>= 1) {
        if (tid < s) sred[tid] += sred[tid + s];
        __syncthreads();
    }
    if (tid == 0) s_lse = logf(sred[0]);
    __syncthreads();
    float lse = s_lse;

    // probs / entropy / gumbel argmax
    float entacc = 0.f;
    float best = -3.402823466e38f;
    int bestv = V;
    size_t pbase = ((size_t)b * L + t) * V;
    const float TINY = 1.17549435e-38f;
    for (int v = tid; v < V; v += 256) {
        float lsm = lr[v] - rowmax - lse;
        float p = expf(lsm);
        o_probs[pbase + v] = p;
        entacc += p * lsm;
        uint32_t o0, o1;
        threefry2x32(sk0, sk1, 0u, (uint32_t)(b * V + v), o0, o1);
        uint32_t bits = o0 ^ o1;
        float uf = __uint_as_float(0x3f800000u | (bits >> 9)) - 1.0f;
        float u = fmaxf(TINY, uf + TINY);
        float g = -logf(-logf(u));
        float sc = lsm + g;
        if (sc > best) { best = sc; bestv = v; }
    }

    // entropy reduce
    __syncthreads();
    sred[tid] = entacc; __syncthreads();
    for (int s = 128; s > 0; s >>= 1) {
        if (tid < s) sred[tid] += sred[tid + s];
        __syncthreads();
    }
    float entropy = -sred[0];
    __syncthreads();

    // argmax reduce (first-index tie-break)
    sred[tid] = best; sredi[tid] = bestv; __syncthreads();
    for (int s = 128; s > 0; s >>= 1) {
        if (tid < s) {
            float ov = sred[tid + s]; int oi = sredi[tid + s];
            if (ov > sred[tid] || (ov == sred[tid] && oi < sredi[tid])) {
                sred[tid] = ov; sredi[tid] = oi;
            }
        }
        __syncthreads();
    }
    if (tid == 0) {
        int sym = sredi[0];
        g_sym[b] = sym;
        o_seq[b * L + t] = (float)sym;
        o_ent[b * L + t] = entropy;
        o_logp[b * L + t] = lr[sym] - rowmax - lse;
    }
}

// ---------------- EOS step (t = 32): zeros + probs of ones ----------------
__global__ void eos_kernel(float* __restrict__ o_seq, float* __restrict__ o_probs,
                           float* __restrict__ o_logp, float* __restrict__ o_ent) {
    int idx = blockIdx.x * blockDim.x + threadIdx.x;
    if (idx < B * V) {
        int b = idx / V, v = idx % V;
        o_probs[((size_t)b * L + MAX_LEN) * V + v] = 1.0f;
    }
    if (idx < B) {
        o_seq[idx * L + MAX_LEN]  = 0.f;
        o_logp[idx * L + MAX_LEN] = 0.f;
        o_ent[idx * L + MAX_LEN]  = 0.f;
    }
}

// ---------------- launch ----------------
extern "C" void kernel_launch(void* const* d_in, const int* in_sizes, int n_in,
                              void* d_out, int out_size) {
    const float* x         = (const float*)d_in[0];
    const float* agent_w   = (const float*)d_in[1];
    const float* agent_b   = (const float*)d_in[2];
    const float* sos       = (const float*)d_in[3];
    const float* embedding = (const float*)d_in[4];
    const float* w_ih      = (const float*)d_in[5];
    const float* w_hh      = (const float*)d_in[6];
    const float* b_ih      = (const float*)d_in[7];
    const float* b_hh      = (const float*)d_in[8];
    const float* out_w     = (const float*)d_in[9];
    const float* out_b     = (const float*)d_in[10];

    float* out = (float*)d_out;
    float* o_seq   = out;                                   // [B, 33]
    float* o_probs = out + (size_t)B * L;                   // [B, 33, V]
    float* o_logp  = o_probs + (size_t)B * L * V;           // [B, 33]
    float* o_ent   = o_logp + (size_t)B * L;                // [B, 33]

    static float *dh = nullptr, *dPg = nullptr, *dl = nullptr, *dep = nullptr;
    if (!dh) {
        cudaGetSymbolAddress((void**)&dh, g_h);
        cudaGetSymbolAddress((void**)&dPg, g_Pg);
        cudaGetSymbolAddress((void**)&dl, g_logits);
        cudaGetSymbolAddress((void**)&dep, g_eproj);
    }

    init_kernel<<<(B * H + 255) / 256, 256>>>();

    // h0 = x @ agent_w + agent_b   (M=512, N=512, K=1024)
    gemm2_kernel<<<dim3(H / BN, B / BM), 256>>>(
        x, IN_DIM, agent_w, agent_b, nullptr, dh, H,
        nullptr, nullptr, nullptr, 0, 0);

    // emb_proj = embedding @ w_ih + b_ih + b_hh   (M=2048, N=2048, K=512)
    gemm2_kernel<<<dim3(G4H / BN, V / BM), 256>>>(
        embedding, E_DIM, w_ih, b_ih, b_hh, dep, G4H,
        nullptr, nullptr, nullptr, 0, 0);

    // sos_proj
    sosproj_kernel<<<G4H / 256, 256>>>(sos, w_ih, b_ih, b_hh);

    // Pg0 = h0 @ w_hh   (M=512, N=2048, K=512)
    gemm2_kernel<<<dim3(G4H / BN, B / BM), 256>>>(
        dh, H, w_hh, nullptr, nullptr, dPg, G4H,
        nullptr, nullptr, nullptr, 0, 0);

    // JAX key chain: key0 = key(1) = (0,1)
    uint32_t k0 = 0u, k1 = 1u;
    for (int t = 0; t < MAX_LEN; ++t) {
        uint32_t n0, n1, s0, s1;
        threefry2x32(k0, k1, 0u, 0u, n0, n1);
        threefry2x32(k0, k1, 0u, 1u, s0, s1);

        // gates = Pg + eproj[sym] -> h, c
        lstm_kernel<<<(B * H + 255) / 256, 256>>>(t);

        // combined: Pg(next) = h@w_hh ; logits = h@out_w + out_b
        if (t < MAX_LEN - 1) {
            gemm2_kernel<<<dim3((G4H + V) / BN, B / BM), 256>>>(
                dh, H, w_hh, nullptr, nullptr, dPg, G4H,
                out_w, out_b, dl, V, 0);
        } else {
            gemm2_kernel<<<dim3(V / BN, B / BM), 256>>>(
                dh, H, w_hh, nullptr, nullptr, dPg, G4H,
                out_w, out_b, dl, V, G4H);
        }

        sample_kernel<<<B, 256>>>(o_seq, o_probs, o_logp, o_ent, s0, s1, t);

        k0 = n0; k1 = n1;
    }

    eos_kernel<<<(B * V + 255) / 256, 256>>>(o_seq, o_probs, o_logp, o_ent);
}